// round 1
// baseline (speedup 1.0000x reference)
#include <cuda_runtime.h>

// ---------------------------------------------------------------------------
// Edge_Labelling: out[e] = tanh(a[src[e]] + b[dst[e]] + c)
// where a[n] = u . f_n, b[n] = v . f_n,
//       u = W1^T (w2a + w2b), v = W1^T (w2b - w2a), c = 2*w2b.b1 + b2
// (exact algebraic collapse of the reference MLP)
// ---------------------------------------------------------------------------

#define D 128
#define MAX_N (1 << 18)   // scratch capacity for node scalars (N = 50000 here)

__device__ __align__(16) float g_u[D];
__device__ __align__(16) float g_v[D];
__device__ float g_a[MAX_N];
__device__ float g_b[MAX_N];
__device__ float g_c;
__device__ int   g_is64;

// --- fold W1, W2, b1, b2 into u, v, c ---------------------------------------
__global__ void k_prep(const float* __restrict__ W1, const float* __restrict__ b1,
                       const float* __restrict__ W2, const float* __restrict__ b2) {
    int d = threadIdx.x;              // 0..127  (input-dim index)
    float au = 0.f, av = 0.f;
    #pragma unroll 8
    for (int o = 0; o < D; ++o) {
        float w  = W1[o * D + d];     // W1 is [D_out, D_in] row-major
        float wa = W2[o];             // w2a
        float wb = W2[D + o];         // w2b
        au = fmaf(w, wa + wb, au);
        av = fmaf(w, wb - wa, av);
    }
    g_u[d] = au;
    g_v[d] = av;
    if (d == 0) {
        float c = b2[0];
        for (int o = 0; o < D; ++o) c = fmaf(2.0f * b1[o], W2[D + o], c);
        g_c = c;
    }
}

// --- detect whether indices are stored as int64 or int32 --------------------
__global__ void k_detect(const long long* __restrict__ src, int N) {
    // If stored as int32, an int64 view combines two random indices and the
    // high word is almost surely nonzero -> value out of [0, N).
    bool all_valid = true;
    #pragma unroll
    for (int i = 0; i < 16; ++i) {
        long long v = src[i];
        if (v < 0 || v >= (long long)N) all_valid = false;
    }
    g_is64 = all_valid ? 1 : 0;
}

// --- per-node dual GEMV: a[n] = u.f_n, b[n] = v.f_n --------------------------
// one warp per node; lane L handles float4 chunk L of the 128-float row
__global__ void k_nodes(const float* __restrict__ feat, int N) {
    int warp = (blockIdx.x * blockDim.x + threadIdx.x) >> 5;
    int lane = threadIdx.x & 31;
    if (warp >= N) return;

    const float4 x = reinterpret_cast<const float4*>(feat + (size_t)warp * D)[lane];
    const float4 u = reinterpret_cast<const float4*>(g_u)[lane];
    const float4 v = reinterpret_cast<const float4*>(g_v)[lane];

    float au = fmaf(x.x, u.x, fmaf(x.y, u.y, fmaf(x.z, u.z, x.w * u.w)));
    float av = fmaf(x.x, v.x, fmaf(x.y, v.y, fmaf(x.z, v.z, x.w * v.w)));

    #pragma unroll
    for (int off = 16; off > 0; off >>= 1) {
        au += __shfl_xor_sync(0xffffffffu, au, off);
        av += __shfl_xor_sync(0xffffffffu, av, off);
    }
    if (lane == 0) {
        g_a[warp] = au;
        g_b[warp] = av;
    }
}

// --- per-edge gather + tanh ---------------------------------------------------
__global__ void k_edges(const void* __restrict__ src_raw, const void* __restrict__ dst_raw,
                        float* __restrict__ out, int E) {
    const float c  = g_c;
    const int is64 = g_is64;
    const int stride = gridDim.x * blockDim.x;
    int e = blockIdx.x * blockDim.x + threadIdx.x;

    if (is64) {
        const long long* s = (const long long*)src_raw;
        const long long* d = (const long long*)dst_raw;
        for (; e < E; e += stride) {
            int si = (int)s[e];
            int di = (int)d[e];
            out[e] = tanhf(__ldg(&g_a[si]) + __ldg(&g_b[di]) + c);
        }
    } else {
        const int* s = (const int*)src_raw;
        const int* d = (const int*)dst_raw;
        for (; e < E; e += stride) {
            int si = s[e];
            int di = d[e];
            out[e] = tanhf(__ldg(&g_a[si]) + __ldg(&g_b[di]) + c);
        }
    }
}

extern "C" void kernel_launch(void* const* d_in, const int* in_sizes, int n_in,
                              void* d_out, int out_size) {
    // inputs: features, src, dst, W1, b1, W2, b2
    const float* feat = (const float*)d_in[0];
    const void*  src  = d_in[1];
    const void*  dst  = d_in[2];
    const float* W1   = (const float*)d_in[3];
    const float* b1   = (const float*)d_in[4];
    const float* W2   = (const float*)d_in[5];
    const float* b2   = (const float*)d_in[6];
    float* out = (float*)d_out;

    const int N = in_sizes[0] / D;   // 50000
    const int E = in_sizes[1];       // 800000

    k_prep<<<1, D>>>(W1, b1, W2, b2);
    k_detect<<<1, 1>>>((const long long*)src, N);

    // 8 warps per block, one node per warp
    const int nodes_per_block = 8;
    int nblocks = (N + nodes_per_block - 1) / nodes_per_block;
    k_nodes<<<nblocks, nodes_per_block * 32>>>(feat, N);

    int eblocks = (E + 255) / 256;
    if (eblocks > 8192) eblocks = 8192;
    k_edges<<<eblocks, 256>>>(src, dst, out, E);
}